// round 8
// baseline (speedup 1.0000x reference)
#include <cuda_runtime.h>
#include <cuda_bf16.h>

#define NMAX   50016
#define EMAX   800000
#define NF     128
#define HH     256
#define OUT2   128
#define NHEADS 4
#define NEG    0.2f

// ---- scratch ----
__device__ float g_h1  [(size_t)NMAX * HH];
__device__ float g_agg1[(size_t)NMAX * HH];
__device__ float g_h2  [(size_t)NMAX * OUT2];
__device__ float g_as1[NMAX * NHEADS];
__device__ float g_ad1[NMAX * NHEADS];
__device__ float g_as2[NMAX];
__device__ float g_ad2[NMAX];
__device__ float g_va1[NF * 8];
__device__ float g_wa2[HH * 2];
__device__ int   g_is64;
// CSR
__device__ int   g_cnt [NMAX + 1];
__device__ int   g_off [NMAX + 1];
__device__ int   g_cur [NMAX + 1];
__device__ int   g_bsum[64];
__device__ int   g_boff[64];
__device__ int   g_csrc[EMAX];
__device__ float g_w1  [(size_t)EMAX * NHEADS];

__device__ __forceinline__ void load_edge(const void* ei, int E, int i,
                                          int& s, int& d) {
    if (g_is64) {
        const long long* p = (const long long*)ei;
        s = (int)p[i]; d = (int)p[(size_t)E + i];
    } else {
        const int* p = (const int*)ei;
        s = p[i]; d = p[E + i];
    }
}

__device__ __forceinline__ float lrelu_exp(float v) {
    v = v > 0.f ? v : NEG * v;
    return __expf(v);
}

#define FMA2(acc, a2, w2) \
    asm("fma.rn.f32x2 %0, %1, %2, %0;" : "+l"(acc) : "l"(a2), "l"(w2))

// ============ KZ: dtype probe + zero counts ============
__global__ void kz(const int* ei32, int E, int n) {
    int i = blockIdx.x * 1024 + threadIdx.x;
    if (i <= n) g_cnt[i] = 0;
    if (blockIdx.x == 0) {
        __shared__ int flag;
        if (threadIdx.x == 0) flag = 0;
        __syncthreads();
        for (int j = threadIdx.x; j < 2048; j += 1024) {
            int idx = 2 * j + 1;
            if (idx < 2 * E && ei32[idx] != 0) flag = 1;
        }
        __syncthreads();
        if (threadIdx.x == 0) g_is64 = (flag == 0);
    }
}

// ============ KC2: count in-degrees ============
__global__ void kc2_count(const void* __restrict__ ei, int E) {
    int i = blockIdx.x * blockDim.x + threadIdx.x;
    if (i >= E) return;
    int s, d; load_edge(ei, E, i, s, d);
    atomicAdd(&g_cnt[d], 1);
}

// ============ KV: attention-vector precomputes ============
__global__ void kv(const float* __restrict__ W1, const float* __restrict__ a_s1,
                   const float* __restrict__ a_d1, const float* __restrict__ W2,
                   const float* __restrict__ a_s2, const float* __restrict__ a_d2) {
    int t = blockIdx.x * 256 + threadIdx.x;
    if (t < NF * 8) {
        int k = t >> 3, o = t & 7, h = o & 3;
        const float* a = (o < 4 ? a_s1 : a_d1) + h * 64;
        const float* w = W1 + (size_t)k * HH + h * 64;
        float s = 0.f;
        #pragma unroll 8
        for (int c = 0; c < 64; c++) s += w[c] * a[c];
        g_va1[t] = s;
    } else if (t < NF * 8 + HH * 2) {
        int q = t - NF * 8;
        int k = q >> 1, o = q & 1;
        const float* a = o ? a_d2 : a_s2;
        const float* w = W2 + (size_t)k * OUT2;
        float s = 0.f;
        #pragma unroll 8
        for (int c = 0; c < OUT2; c++) s += w[c] * a[c];
        g_wa2[q] = s;
    }
}

// ============ K1: h1 = x @ W1 (smem-staged W, dup-operand f32x2) ============
// dyn smem: xs2[32][260] dup tile | sW[32][256] W-quarter | sva[1024]
#define K1_XS2   (32 * 260)
#define K1_SW    (32 * 256)
#define K1_SMEM  ((K1_XS2 + K1_SW + NF * 8) * 4)
__global__ void k1_gemm1(const float* __restrict__ x, const float* __restrict__ W1,
                         int n_nodes) {
    extern __shared__ float sm[];
    float* xs2 = sm;                  // dup k-pairs, row stride 260
    float* sW  = sm + K1_XS2;         // [32][256] current k-quarter
    float* sva = sm + K1_XS2 + K1_SW;
    const int n0 = blockIdx.x * 32;
    const int tid = threadIdx.x;      // 256
    for (int i = tid; i < NF * 8; i += 256) sva[i] = g_va1[i];
    #pragma unroll
    for (int r = 0; r < 4; r++) {
        int i = tid + r * 256;        // 1024 tasks: 32 nodes x 32 float4s
        int nn = i >> 5, k4 = i & 31;
        int g = n0 + nn;
        float4 v = make_float4(0.f, 0.f, 0.f, 0.f);
        if (g < n_nodes) v = *reinterpret_cast<const float4*>(x + (size_t)g * NF + 4 * k4);
        float4 lo = make_float4(v.x, v.x, v.y, v.y);
        float4 hi = make_float4(v.z, v.z, v.w, v.w);
        *reinterpret_cast<float4*>(&xs2[nn * 260 + 8 * k4])     = lo;
        *reinterpret_cast<float4*>(&xs2[nn * 260 + 8 * k4 + 4]) = hi;
    }
    const int tx = tid & 63, ty = tid >> 6;   // cols 4tx..4tx+3, nodes ty*8+t
    unsigned long long acc[8][2] = {};
    #pragma unroll
    for (int q = 0; q < 4; q++) {             // k-quarters of 32
        __syncthreads();
        #pragma unroll
        for (int r = 0; r < 8; r++) {         // 2048 float4s: 32 krows x 64 col4s
            int i = tid + r * 256;
            int kk = i >> 6, c4 = i & 63;
            *reinterpret_cast<float4*>(&sW[kk * 256 + 4 * c4]) =
                *reinterpret_cast<const float4*>(W1 + (size_t)(q * 32 + kk) * HH + 4 * c4);
        }
        __syncthreads();
        #pragma unroll 4
        for (int k2 = 0; k2 < 32; k2 += 2) {
            ulonglong2 wa = *reinterpret_cast<const ulonglong2*>(&sW[k2 * 256 + 4 * tx]);
            ulonglong2 wb = *reinterpret_cast<const ulonglong2*>(&sW[(k2 + 1) * 256 + 4 * tx]);
            int kg = q * 32 + k2;
            #pragma unroll
            for (int t = 0; t < 8; t++) {
                ulonglong2 ap = *reinterpret_cast<const ulonglong2*>(
                    &xs2[(ty * 8 + t) * 260 + 2 * kg]);
                FMA2(acc[t][0], ap.x, wa.x);
                FMA2(acc[t][1], ap.x, wa.y);
                FMA2(acc[t][0], ap.y, wb.x);
                FMA2(acc[t][1], ap.y, wb.y);
            }
        }
    }
    #pragma unroll
    for (int t = 0; t < 8; t++) {
        int g = n0 + ty * 8 + t;
        if (g < n_nodes) {
            float4 o;
            o.x = __uint_as_float((unsigned)(acc[t][0]));
            o.y = __uint_as_float((unsigned)(acc[t][0] >> 32));
            o.z = __uint_as_float((unsigned)(acc[t][1]));
            o.w = __uint_as_float((unsigned)(acc[t][1] >> 32));
            *reinterpret_cast<float4*>(g_h1 + (size_t)g * HH + 4 * tx) = o;
        }
    }
    // fused layer-1 logits: 256 threads = 32 nodes x 8 outputs
    {
        int nn = tid >> 3, o = tid & 7;
        int g = n0 + nn;
        float s = 0.f;
        #pragma unroll 8
        for (int k = 0; k < NF; k++) s += xs2[nn * 260 + 2 * k] * sva[k * 8 + o];
        if (g < n_nodes) {
            if (o < 4) g_as1[g * 4 + o] = s;
            else       g_ad1[g * 4 + o - 4] = s;
        }
    }
}

// ============ scan ============
__global__ void s1_scan(int n) {
    __shared__ int sd[1024];
    int tid = threadIdx.x;
    int i = blockIdx.x * 1024 + tid;
    int v = (i < n) ? g_cnt[i] : 0;
    sd[tid] = v;
    __syncthreads();
    #pragma unroll
    for (int off = 1; off < 1024; off <<= 1) {
        int t = (tid >= off) ? sd[tid - off] : 0;
        __syncthreads();
        sd[tid] += t;
        __syncthreads();
    }
    if (i < n) g_off[i] = sd[tid] - v;
    if (tid == 1023) g_bsum[blockIdx.x] = sd[1023];
}
__global__ void s2_scan(int nb) {
    if (threadIdx.x == 0) {
        int acc = 0;
        for (int b = 0; b < nb; b++) { int t = g_bsum[b]; g_boff[b] = acc; acc += t; }
    }
}
__global__ void s3_scan(int n, int E) {
    int i = blockIdx.x * 1024 + threadIdx.x;
    if (i < n) {
        int v = g_off[i] + g_boff[blockIdx.x];
        g_off[i] = v;
        g_cur[i] = v;
    }
    if (i == 0) g_off[n] = E;
}

// ============ KC3W1: CSR fill + layer-1 softmax numerators ============
__global__ void kc3w1(const void* __restrict__ ei, int E) {
    int i = blockIdx.x * blockDim.x + threadIdx.x;
    if (i >= E) return;
    int s, d; load_edge(ei, E, i, s, d);
    int p = atomicAdd(&g_cur[d], 1);
    g_csrc[p] = s;
    float4 as = *reinterpret_cast<const float4*>(g_as1 + 4 * s);
    float4 ad = *reinterpret_cast<const float4*>(g_ad1 + 4 * d);
    float4 w;
    w.x = lrelu_exp(as.x + ad.x);
    w.y = lrelu_exp(as.y + ad.y);
    w.z = lrelu_exp(as.z + ad.z);
    w.w = lrelu_exp(as.w + ad.w);
    *reinterpret_cast<float4*>(g_w1 + (size_t)p * 4) = w;
}

// ============ KA1: gather aggregation, layer 1 (smem-staged edges) ============
__global__ void ka1(int n_nodes) {
    __shared__ int   ssrc[128];
    __shared__ float sw[128 * 4];
    const int d = blockIdx.x;
    const int j = threadIdx.x;    // 256
    const int h = j >> 6;
    float w0 = lrelu_exp(g_as1[d * NHEADS + h] + g_ad1[d * NHEADS + h]);
    float den = w0;
    float acc = w0 * g_h1[(size_t)d * HH + j];
    const int pB = g_off[d], pE = g_off[d + 1];
    for (int p0 = pB; p0 < pE; p0 += 128) {
        int np = min(128, pE - p0);
        __syncthreads();
        if (j < np) {
            ssrc[j] = g_csrc[p0 + j];
        } else if (j >= 128 && j - 128 < np) {
            int e = j - 128;
            *reinterpret_cast<float4*>(&sw[4 * e]) =
                *reinterpret_cast<const float4*>(g_w1 + (size_t)(p0 + e) * 4);
        }
        __syncthreads();
        #pragma unroll 4
        for (int e = 0; e < np; e++) {
            int s = ssrc[e];
            float wp = sw[4 * e + h];
            den += wp;
            acc += wp * g_h1[(size_t)s * HH + j];
        }
    }
    g_agg1[(size_t)d * HH + j] = acc / den;
}

// ============ K4: h2 = elu(agg1+b1) @ W2 (smem-staged W, f32x2) + logits ============
// dyn smem: xs2[32][260] (one k-half dup) | sW[32][128] | swa[512]
#define K4_XS2   (32 * 260)
#define K4_SW    (32 * 128)
#define K4_SMEM  ((K4_XS2 + K4_SW + HH * 2) * 4)
__global__ void k4_gemm2(const float* __restrict__ W2, const float* __restrict__ b1,
                         int n_nodes) {
    extern __shared__ float sm[];
    float* xs2 = sm;
    float* sW  = sm + K4_XS2;
    float* swa = sm + K4_XS2 + K4_SW;
    const int n0 = blockIdx.x * 32;
    const int tid = threadIdx.x;            // 256
    for (int i = tid; i < HH * 2; i += 256) swa[i] = g_wa2[i];
    const int tx = tid & 31, ty = tid >> 5; // cols 4tx..4tx+3, nodes ty*4+t
    unsigned long long acc[4][2] = {};
    float ls = 0.f;
    #pragma unroll
    for (int half = 0; half < 2; half++) {
        const int kbase = half * 128;
        __syncthreads();
        #pragma unroll
        for (int r = 0; r < 4; r++) {
            int i = tid + r * 256;          // 1024 tasks: 32 nodes x 32 float4s
            int nn = i >> 5, k4 = i & 31;
            int g = n0 + nn;
            float4 v = make_float4(0.f, 0.f, 0.f, 0.f);
            if (g < n_nodes) {
                int kk = kbase + 4 * k4;
                v = *reinterpret_cast<const float4*>(g_agg1 + (size_t)g * HH + kk);
                float4 b = *reinterpret_cast<const float4*>(b1 + kk);
                v.x += b.x; v.y += b.y; v.z += b.z; v.w += b.w;
                v.x = v.x > 0.f ? v.x : expm1f(v.x);
                v.y = v.y > 0.f ? v.y : expm1f(v.y);
                v.z = v.z > 0.f ? v.z : expm1f(v.z);
                v.w = v.w > 0.f ? v.w : expm1f(v.w);
            }
            float4 lo = make_float4(v.x, v.x, v.y, v.y);
            float4 hi = make_float4(v.z, v.z, v.w, v.w);
            *reinterpret_cast<float4*>(&xs2[nn * 260 + 8 * k4])     = lo;
            *reinterpret_cast<float4*>(&xs2[nn * 260 + 8 * k4 + 4]) = hi;
        }
        __syncthreads();
        // logits partial over this k-half
        if (tid < 64) {
            int nn = tid >> 1, o = tid & 1;
            #pragma unroll 8
            for (int k = 0; k < 128; k++)
                ls += xs2[nn * 260 + 2 * k] * swa[2 * (kbase + k) + o];
        }
        #pragma unroll
        for (int q = 0; q < 4; q++) {       // W quarters: 32 krows x 128 cols
            __syncthreads();
            #pragma unroll
            for (int r = 0; r < 4; r++) {   // 1024 float4s
                int i = tid + r * 256;
                int kk = i >> 5, c4 = i & 31;
                *reinterpret_cast<float4*>(&sW[kk * 128 + 4 * c4]) =
                    *reinterpret_cast<const float4*>(
                        W2 + (size_t)(kbase + q * 32 + kk) * OUT2 + 4 * c4);
            }
            __syncthreads();
            #pragma unroll 4
            for (int k2 = 0; k2 < 32; k2 += 2) {
                ulonglong2 wa = *reinterpret_cast<const ulonglong2*>(&sW[k2 * 128 + 4 * tx]);
                ulonglong2 wb = *reinterpret_cast<const ulonglong2*>(&sW[(k2 + 1) * 128 + 4 * tx]);
                int kl = q * 32 + k2;       // k within half
                #pragma unroll
                for (int t = 0; t < 4; t++) {
                    ulonglong2 ap = *reinterpret_cast<const ulonglong2*>(
                        &xs2[(ty * 4 + t) * 260 + 2 * kl]);
                    FMA2(acc[t][0], ap.x, wa.x);
                    FMA2(acc[t][1], ap.x, wa.y);
                    FMA2(acc[t][0], ap.y, wb.x);
                    FMA2(acc[t][1], ap.y, wb.y);
                }
            }
        }
    }
    #pragma unroll
    for (int t = 0; t < 4; t++) {
        int g = n0 + ty * 4 + t;
        if (g < n_nodes) {
            float4 o;
            o.x = __uint_as_float((unsigned)(acc[t][0]));
            o.y = __uint_as_float((unsigned)(acc[t][0] >> 32));
            o.z = __uint_as_float((unsigned)(acc[t][1]));
            o.w = __uint_as_float((unsigned)(acc[t][1] >> 32));
            *reinterpret_cast<float4*>(g_h2 + (size_t)g * OUT2 + 4 * tx) = o;
        }
    }
    if (tid < 64) {
        int nn = tid >> 1, o = tid & 1;
        int g = n0 + nn;
        if (g < n_nodes) {
            if (o == 0) g_as2[g] = ls;
            else        g_ad2[g] = ls;
        }
    }
}

// ============ KA2: gather aggregation, layer 2 ============
__global__ void ka2(int n_nodes, const float* __restrict__ b2,
                    float* __restrict__ out) {
    __shared__ int   ssrc[128];
    __shared__ float sw[128];
    const int d = blockIdx.x;
    const int j = threadIdx.x;   // 128
    float add = g_ad2[d];
    float w0 = lrelu_exp(g_as2[d] + add);
    float den = w0;
    float acc = w0 * g_h2[(size_t)d * OUT2 + j];
    const int pB = g_off[d], pE = g_off[d + 1];
    for (int p0 = pB; p0 < pE; p0 += 128) {
        int np = min(128, pE - p0);
        __syncthreads();
        if (j < np) {
            int s = g_csrc[p0 + j];
            ssrc[j] = s;
            sw[j] = lrelu_exp(g_as2[s] + add);
        }
        __syncthreads();
        #pragma unroll 4
        for (int e = 0; e < np; e++) {
            int s = ssrc[e];
            float wp = sw[e];
            den += wp;
            acc += wp * g_h2[(size_t)s * OUT2 + j];
        }
    }
    out[(size_t)d * OUT2 + j] = acc / den + b2[j];
}

extern "C" void kernel_launch(void* const* d_in, const int* in_sizes, int n_in,
                              void* d_out, int out_size) {
    const float* x    = (const float*)d_in[0];
    const void*  ei   = d_in[1];
    const float* W1   = (const float*)d_in[2];
    const float* as1  = (const float*)d_in[3];
    const float* ad1  = (const float*)d_in[4];
    const float* b1   = (const float*)d_in[5];
    const float* W2   = (const float*)d_in[6];
    const float* as2  = (const float*)d_in[7];
    const float* ad2  = (const float*)d_in[8];
    const float* b2   = (const float*)d_in[9];
    float* out = (float*)d_out;

    const int n_nodes = in_sizes[0] / NF;
    const int E  = in_sizes[1] / 2;

    const int gemm_blocks = (n_nodes + 31) / 32;
    const int eb = (E + 255) / 256;
    const int nb = (n_nodes + 1023) / 1024;

    static int smem_set = 0;
    if (!smem_set) {
        cudaFuncSetAttribute(k1_gemm1, cudaFuncAttributeMaxDynamicSharedMemorySize, K1_SMEM);
        cudaFuncSetAttribute(k4_gemm2, cudaFuncAttributeMaxDynamicSharedMemorySize, K4_SMEM);
        smem_set = 1;
    }

    kz<<<nb + 1, 1024>>>((const int*)ei, E, n_nodes);          // 1
    kc2_count<<<eb, 256>>>(ei, E);                             // 2
    kv<<<6, 256>>>(W1, as1, ad1, W2, as2, ad2);                // 3
    k1_gemm1<<<gemm_blocks, 256, K1_SMEM>>>(x, W1, n_nodes);   // 4  <- profiled slot
    s1_scan<<<nb, 1024>>>(n_nodes);                            // 5
    s2_scan<<<1, 32>>>(nb);                                    // 6
    s3_scan<<<nb, 1024>>>(n_nodes, E);                         // 7
    kc3w1<<<eb, 256>>>(ei, E);                                 // 8
    ka1<<<n_nodes, 256>>>(n_nodes);                            // 9
    k4_gemm2<<<gemm_blocks, 256, K4_SMEM>>>(W2, b1, n_nodes);  // 10
    ka2<<<n_nodes, 128>>>(n_nodes, b2, out);                   // 11
}

// round 9
// speedup vs baseline: 1.0289x; 1.0289x over previous
#include <cuda_runtime.h>
#include <cuda_bf16.h>

#define NMAX   50016
#define EMAX   800000
#define NF     128
#define HH     256
#define OUT2   128
#define NHEADS 4
#define NEG    0.2f

// ---- scratch ----
__device__ float g_h1  [(size_t)NMAX * HH];
__device__ float g_agg1[(size_t)NMAX * HH];
__device__ float g_h2  [(size_t)NMAX * OUT2];
__device__ float g_as1[NMAX * NHEADS];
__device__ float g_ad1[NMAX * NHEADS];
__device__ float g_as2[NMAX];
__device__ float g_ad2[NMAX];
__device__ float g_va1[NF * 8];
__device__ float g_wa2[HH * 2];
__device__ int   g_is64;
// CSR
__device__ int   g_cnt [NMAX + 1];
__device__ int   g_off [NMAX + 1];
__device__ int   g_cur [NMAX + 1];
__device__ int   g_bsum[64];
__device__ int   g_boff[64];
__device__ int   g_csrc[EMAX];
__device__ float g_w1  [(size_t)EMAX * NHEADS];

__device__ __forceinline__ void load_edge(const void* ei, int E, int i,
                                          int& s, int& d) {
    if (g_is64) {
        const long long* p = (const long long*)ei;
        s = (int)p[i]; d = (int)p[(size_t)E + i];
    } else {
        const int* p = (const int*)ei;
        s = p[i]; d = p[E + i];
    }
}

__device__ __forceinline__ float lrelu_exp(float v) {
    v = v > 0.f ? v : NEG * v;
    return __expf(v);
}

#define FMA2(acc, a2, w2) \
    asm("fma.rn.f32x2 %0, %1, %2, %0;" : "+l"(acc) : "l"(a2), "l"(w2))

#define MMA_BF16(c0,c1,c2,c3,a0,a1,a2,a3,b0,b1) \
    asm("mma.sync.aligned.m16n8k16.row.col.f32.bf16.bf16.f32 " \
        "{%0,%1,%2,%3}, {%4,%5,%6,%7}, {%8,%9}, {%0,%1,%2,%3};" \
        : "+f"(c0), "+f"(c1), "+f"(c2), "+f"(c3) \
        : "r"(a0), "r"(a1), "r"(a2), "r"(a3), "r"(b0), "r"(b1))

__device__ __forceinline__ unsigned bf16_hi_pack(float a, float b) {
    __nv_bfloat16 ha = __float2bfloat16(a), hb = __float2bfloat16(b);
    unsigned ua, ub;
    ua = (unsigned)__bfloat16_as_ushort(ha);
    ub = (unsigned)__bfloat16_as_ushort(hb);
    return ua | (ub << 16);
}
__device__ __forceinline__ unsigned bf16_lo_pack(float a, float b) {
    float ra = a - __bfloat162float(__float2bfloat16(a));
    float rb = b - __bfloat162float(__float2bfloat16(b));
    return bf16_hi_pack(ra, rb);
}

// ============ KZ: dtype probe + zero counts ============
__global__ void kz(const int* ei32, int E, int n) {
    int i = blockIdx.x * 1024 + threadIdx.x;
    if (i <= n) g_cnt[i] = 0;
    if (blockIdx.x == 0) {
        __shared__ int flag;
        if (threadIdx.x == 0) flag = 0;
        __syncthreads();
        for (int j = threadIdx.x; j < 2048; j += 1024) {
            int idx = 2 * j + 1;
            if (idx < 2 * E && ei32[idx] != 0) flag = 1;
        }
        __syncthreads();
        if (threadIdx.x == 0) g_is64 = (flag == 0);
    }
}

// ============ KC2: count in-degrees ============
__global__ void kc2_count(const void* __restrict__ ei, int E) {
    int i = blockIdx.x * blockDim.x + threadIdx.x;
    if (i >= E) return;
    int s, d; load_edge(ei, E, i, s, d);
    atomicAdd(&g_cnt[d], 1);
}

// ============ KV: attention-vector precomputes ============
__global__ void kv(const float* __restrict__ W1, const float* __restrict__ a_s1,
                   const float* __restrict__ a_d1, const float* __restrict__ W2,
                   const float* __restrict__ a_s2, const float* __restrict__ a_d2) {
    int t = blockIdx.x * 256 + threadIdx.x;
    if (t < NF * 8) {
        int k = t >> 3, o = t & 7, h = o & 3;
        const float* a = (o < 4 ? a_s1 : a_d1) + h * 64;
        const float* w = W1 + (size_t)k * HH + h * 64;
        float s = 0.f;
        #pragma unroll 8
        for (int c = 0; c < 64; c++) s += w[c] * a[c];
        g_va1[t] = s;
    } else if (t < NF * 8 + HH * 2) {
        int q = t - NF * 8;
        int k = q >> 1, o = q & 1;
        const float* a = o ? a_d2 : a_s2;
        const float* w = W2 + (size_t)k * OUT2;
        float s = 0.f;
        #pragma unroll 8
        for (int c = 0; c < OUT2; c++) s += w[c] * a[c];
        g_wa2[q] = s;
    }
}

// ============ K1: h1 = x @ W1  (bf16-split tensor-core MMA) ============
// Block: 64 rows x 64 cols, 256 threads (8 warps = 4 row x 2 col).
// dyn smem (bf16, rows padded to 136): Xhi[64][136] Xlo[64][136] Whi[64][136] Wlo[64][136]
#define K1_PAD   136
#define K1_XSZ   (64 * K1_PAD)          // bf16 elems per tile
#define K1_SMEM  (4 * K1_XSZ * 2)       // bytes = 69632
__global__ void k1_gemm1(const float* __restrict__ x, const float* __restrict__ W1,
                         int n_nodes) {
    extern __shared__ __nv_bfloat16 smb[];
    __nv_bfloat16* Xhi = smb;
    __nv_bfloat16* Xlo = smb + K1_XSZ;
    __nv_bfloat16* Whi = smb + 2 * K1_XSZ;
    __nv_bfloat16* Wlo = smb + 3 * K1_XSZ;
    const int n0 = blockIdx.x * 64;
    const int c0 = blockIdx.y * 64;
    const int tid = threadIdx.x;          // 256

    // load X tile (64 rows x 128 k), split hi/lo
    #pragma unroll
    for (int r = 0; r < 8; r++) {
        int i = tid + r * 256;            // 2048 tasks: 64 rows x 32 float4
        int nn = i >> 5, k4 = i & 31;
        int g = n0 + nn;
        float4 v = make_float4(0.f, 0.f, 0.f, 0.f);
        if (g < n_nodes) v = *reinterpret_cast<const float4*>(x + (size_t)g * NF + 4 * k4);
        uint2 hp, lp;
        hp.x = bf16_hi_pack(v.x, v.y); hp.y = bf16_hi_pack(v.z, v.w);
        lp.x = bf16_lo_pack(v.x, v.y); lp.y = bf16_lo_pack(v.z, v.w);
        *reinterpret_cast<uint2*>(&Xhi[nn * K1_PAD + 4 * k4]) = hp;
        *reinterpret_cast<uint2*>(&Xlo[nn * K1_PAD + 4 * k4]) = lp;
    }
    // load W slab (128 k x 64 cols), transpose to [col][k], split hi/lo
    #pragma unroll
    for (int r = 0; r < 8; r++) {
        int i = tid + r * 256;            // 2048 tasks: 128 k x 16 float4
        int k = i >> 4, c4 = i & 15;
        float4 w = *reinterpret_cast<const float4*>(W1 + (size_t)k * HH + c0 + 4 * c4);
        int cb = 4 * c4;
        Whi[(cb + 0) * K1_PAD + k] = __float2bfloat16(w.x);
        Whi[(cb + 1) * K1_PAD + k] = __float2bfloat16(w.y);
        Whi[(cb + 2) * K1_PAD + k] = __float2bfloat16(w.z);
        Whi[(cb + 3) * K1_PAD + k] = __float2bfloat16(w.w);
        Wlo[(cb + 0) * K1_PAD + k] = __float2bfloat16(w.x - __bfloat162float(__float2bfloat16(w.x)));
        Wlo[(cb + 1) * K1_PAD + k] = __float2bfloat16(w.y - __bfloat162float(__float2bfloat16(w.y)));
        Wlo[(cb + 2) * K1_PAD + k] = __float2bfloat16(w.z - __bfloat162float(__float2bfloat16(w.z)));
        Wlo[(cb + 3) * K1_PAD + k] = __float2bfloat16(w.w - __bfloat162float(__float2bfloat16(w.w)));
    }
    __syncthreads();

    const int wid = tid >> 5, lane = tid & 31;
    const int wr = (wid >> 1) * 16;       // warp row base (0,16,32,48)
    const int wc = (wid & 1) * 32;        // warp col base (0,32)
    const int gq = lane >> 2, tg = lane & 3;

    float C[4][4] = {};
    #pragma unroll
    for (int ks = 0; ks < 8; ks++) {
        const int k0 = ks * 16;
        unsigned ah[4], al[4];
        const __nv_bfloat16* xa = Xhi + (wr + gq) * K1_PAD + k0 + 2 * tg;
        ah[0] = *reinterpret_cast<const unsigned*>(xa);
        ah[1] = *reinterpret_cast<const unsigned*>(xa + 8 * K1_PAD);
        ah[2] = *reinterpret_cast<const unsigned*>(xa + 8);
        ah[3] = *reinterpret_cast<const unsigned*>(xa + 8 * K1_PAD + 8);
        const __nv_bfloat16* xb = Xlo + (wr + gq) * K1_PAD + k0 + 2 * tg;
        al[0] = *reinterpret_cast<const unsigned*>(xb);
        al[1] = *reinterpret_cast<const unsigned*>(xb + 8 * K1_PAD);
        al[2] = *reinterpret_cast<const unsigned*>(xb + 8);
        al[3] = *reinterpret_cast<const unsigned*>(xb + 8 * K1_PAD + 8);
        #pragma unroll
        for (int ns = 0; ns < 4; ns++) {
            const __nv_bfloat16* wa = Whi + (wc + ns * 8 + gq) * K1_PAD + k0 + 2 * tg;
            unsigned bh0 = *reinterpret_cast<const unsigned*>(wa);
            unsigned bh1 = *reinterpret_cast<const unsigned*>(wa + 8);
            const __nv_bfloat16* wb = Wlo + (wc + ns * 8 + gq) * K1_PAD + k0 + 2 * tg;
            unsigned bl0 = *reinterpret_cast<const unsigned*>(wb);
            unsigned bl1 = *reinterpret_cast<const unsigned*>(wb + 8);
            MMA_BF16(C[ns][0], C[ns][1], C[ns][2], C[ns][3],
                     ah[0], ah[1], ah[2], ah[3], bh0, bh1);
            MMA_BF16(C[ns][0], C[ns][1], C[ns][2], C[ns][3],
                     ah[0], ah[1], ah[2], ah[3], bl0, bl1);
            MMA_BF16(C[ns][0], C[ns][1], C[ns][2], C[ns][3],
                     al[0], al[1], al[2], al[3], bh0, bh1);
        }
    }
    // epilogue: C[ns] rows (wr+gq, wr+gq+8), cols wc+ns*8+2tg..+1
    #pragma unroll
    for (int ns = 0; ns < 4; ns++) {
        int col = c0 + wc + ns * 8 + 2 * tg;
        int r0 = n0 + wr + gq;
        if (r0 < n_nodes) {
            float2 v = make_float2(C[ns][0], C[ns][1]);
            *reinterpret_cast<float2*>(g_h1 + (size_t)r0 * HH + col) = v;
        }
        if (r0 + 8 < n_nodes) {
            float2 v = make_float2(C[ns][2], C[ns][3]);
            *reinterpret_cast<float2*>(g_h1 + (size_t)(r0 + 8) * HH + col) = v;
        }
    }
}

// ============ KS1: layer-1 logits  as1/ad1 = x @ va1 ============
__global__ void ks_alpha1(const float* __restrict__ x, int n_nodes) {
    __shared__ float xv[32][NF];
    __shared__ float sva[NF * 8];
    const int n0 = blockIdx.x * 32;
    const int tid = threadIdx.x;      // 256
    for (int i = tid; i < NF * 8; i += 256) sva[i] = g_va1[i];
    #pragma unroll
    for (int r = 0; r < 4; r++) {
        int i = tid + r * 256;
        int nn = i >> 5, k4 = i & 31;
        int g = n0 + nn;
        float4 v = make_float4(0.f, 0.f, 0.f, 0.f);
        if (g < n_nodes) v = *reinterpret_cast<const float4*>(x + (size_t)g * NF + 4 * k4);
        *reinterpret_cast<float4*>(&xv[nn][4 * k4]) = v;
    }
    __syncthreads();
    int nn = tid >> 3, o = tid & 7;
    int g = n0 + nn;
    float s = 0.f;
    #pragma unroll 8
    for (int k = 0; k < NF; k++) s += xv[nn][k] * sva[k * 8 + o];
    if (g < n_nodes) {
        if (o < 4) g_as1[g * 4 + o] = s;
        else       g_ad1[g * 4 + o - 4] = s;
    }
}

// ============ scan ============
__global__ void s1_scan(int n) {
    __shared__ int sd[1024];
    int tid = threadIdx.x;
    int i = blockIdx.x * 1024 + tid;
    int v = (i < n) ? g_cnt[i] : 0;
    sd[tid] = v;
    __syncthreads();
    #pragma unroll
    for (int off = 1; off < 1024; off <<= 1) {
        int t = (tid >= off) ? sd[tid - off] : 0;
        __syncthreads();
        sd[tid] += t;
        __syncthreads();
    }
    if (i < n) g_off[i] = sd[tid] - v;
    if (tid == 1023) g_bsum[blockIdx.x] = sd[1023];
}
__global__ void s2_scan(int nb) {
    if (threadIdx.x == 0) {
        int acc = 0;
        for (int b = 0; b < nb; b++) { int t = g_bsum[b]; g_boff[b] = acc; acc += t; }
    }
}
__global__ void s3_scan(int n, int E) {
    int i = blockIdx.x * 1024 + threadIdx.x;
    if (i < n) {
        int v = g_off[i] + g_boff[blockIdx.x];
        g_off[i] = v;
        g_cur[i] = v;
    }
    if (i == 0) g_off[n] = E;
}

// ============ KC3W1: CSR fill + layer-1 softmax numerators ============
__global__ void kc3w1(const void* __restrict__ ei, int E) {
    int i = blockIdx.x * blockDim.x + threadIdx.x;
    if (i >= E) return;
    int s, d; load_edge(ei, E, i, s, d);
    int p = atomicAdd(&g_cur[d], 1);
    g_csrc[p] = s;
    float4 as = *reinterpret_cast<const float4*>(g_as1 + 4 * s);
    float4 ad = *reinterpret_cast<const float4*>(g_ad1 + 4 * d);
    float4 w;
    w.x = lrelu_exp(as.x + ad.x);
    w.y = lrelu_exp(as.y + ad.y);
    w.z = lrelu_exp(as.z + ad.z);
    w.w = lrelu_exp(as.w + ad.w);
    *reinterpret_cast<float4*>(g_w1 + (size_t)p * 4) = w;
}

// ============ KA1: gather aggregation, layer 1 (smem-staged edges) ============
__global__ void ka1(int n_nodes) {
    __shared__ int   ssrc[128];
    __shared__ float sw[128 * 4];
    const int d = blockIdx.x;
    const int j = threadIdx.x;    // 256
    const int h = j >> 6;
    float w0 = lrelu_exp(g_as1[d * NHEADS + h] + g_ad1[d * NHEADS + h]);
    float den = w0;
    float acc = w0 * g_h1[(size_t)d * HH + j];
    const int pB = g_off[d], pE = g_off[d + 1];
    for (int p0 = pB; p0 < pE; p0 += 128) {
        int np = min(128, pE - p0);
        __syncthreads();
        if (j < np) {
            ssrc[j] = g_csrc[p0 + j];
        } else if (j >= 128 && j - 128 < np) {
            int e = j - 128;
            *reinterpret_cast<float4*>(&sw[4 * e]) =
                *reinterpret_cast<const float4*>(g_w1 + (size_t)(p0 + e) * 4);
        }
        __syncthreads();
        #pragma unroll 4
        for (int e = 0; e < np; e++) {
            int s = ssrc[e];
            float wp = sw[4 * e + h];
            den += wp;
            acc += wp * g_h1[(size_t)s * HH + j];
        }
    }
    g_agg1[(size_t)d * HH + j] = acc / den;
}

// ============ K4: h2 = elu(agg1+b1) @ W2 (dup-operand f32x2) + logits ============
__global__ void k4_gemm2(const float* __restrict__ W2, const float* __restrict__ b1,
                         int n_nodes) {
    __shared__ float xs2[32][2 * 128 + 4];
    __shared__ float swa[HH * 2];
    const int n0 = blockIdx.x * 32;
    const int tid = threadIdx.x;            // 256
    for (int i = tid; i < HH * 2; i += 256) swa[i] = g_wa2[i];
    const int tx = tid & 31, ty = tid >> 5;
    unsigned long long acc[4][2] = {};
    float ls = 0.f;
    #pragma unroll
    for (int half = 0; half < 2; half++) {
        const int kbase = half * 128;
        __syncthreads();
        #pragma unroll
        for (int r = 0; r < 4; r++) {
            int i = tid + r * 256;
            int nn = i >> 5, k4 = i & 31;
            int g = n0 + nn;
            float4 v = make_float4(0.f, 0.f, 0.f, 0.f);
            if (g < n_nodes) {
                int kk = kbase + 4 * k4;
                v = *reinterpret_cast<const float4*>(g_agg1 + (size_t)g * HH + kk);
                float4 b = *reinterpret_cast<const float4*>(b1 + kk);
                v.x += b.x; v.y += b.y; v.z += b.z; v.w += b.w;
                v.x = v.x > 0.f ? v.x : expm1f(v.x);
                v.y = v.y > 0.f ? v.y : expm1f(v.y);
                v.z = v.z > 0.f ? v.z : expm1f(v.z);
                v.w = v.w > 0.f ? v.w : expm1f(v.w);
            }
            float4 lo = make_float4(v.x, v.x, v.y, v.y);
            float4 hi = make_float4(v.z, v.z, v.w, v.w);
            *reinterpret_cast<float4*>(&xs2[nn][8 * k4])     = lo;
            *reinterpret_cast<float4*>(&xs2[nn][8 * k4 + 4]) = hi;
        }
        __syncthreads();
        const float* wp = W2 + (size_t)kbase * OUT2 + 4 * tx;
        #pragma unroll 2
        for (int k2 = 0; k2 < 128; k2 += 2) {
            ulonglong2 wa = *reinterpret_cast<const ulonglong2*>(wp + (size_t)k2 * OUT2);
            ulonglong2 wb = *reinterpret_cast<const ulonglong2*>(wp + (size_t)(k2 + 1) * OUT2);
            #pragma unroll
            for (int t = 0; t < 4; t++) {
                ulonglong2 ap = *reinterpret_cast<const ulonglong2*>(&xs2[ty * 4 + t][2 * k2]);
                FMA2(acc[t][0], ap.x, wa.x);
                FMA2(acc[t][1], ap.x, wa.y);
                FMA2(acc[t][0], ap.y, wb.x);
                FMA2(acc[t][1], ap.y, wb.y);
            }
        }
        if (tid < 64) {
            int nn = tid >> 1, o = tid & 1;
            #pragma unroll 8
            for (int k = 0; k < 128; k++)
                ls += xs2[nn][2 * k] * swa[2 * (kbase + k) + o];
        }
    }
    #pragma unroll
    for (int t = 0; t < 4; t++) {
        int g = n0 + ty * 4 + t;
        if (g < n_nodes) {
            float4 o;
            o.x = __uint_as_float((unsigned)(acc[t][0]));
            o.y = __uint_as_float((unsigned)(acc[t][0] >> 32));
            o.z = __uint_as_float((unsigned)(acc[t][1]));
            o.w = __uint_as_float((unsigned)(acc[t][1] >> 32));
            *reinterpret_cast<float4*>(g_h2 + (size_t)g * OUT2 + 4 * tx) = o;
        }
    }
    if (tid < 64) {
        int nn = tid >> 1, o = tid & 1;
        int g = n0 + nn;
        if (g < n_nodes) {
            if (o == 0) g_as2[g] = ls;
            else        g_ad2[g] = ls;
        }
    }
}

// ============ KA2: gather aggregation, layer 2 ============
__global__ void ka2(int n_nodes, const float* __restrict__ b2,
                    float* __restrict__ out) {
    __shared__ int   ssrc[128];
    __shared__ float sw[128];
    const int d = blockIdx.x;
    const int j = threadIdx.x;   // 128
    float add = g_ad2[d];
    float w0 = lrelu_exp(g_as2[d] + add);
    float den = w0;
    float acc = w0 * g_h2[(size_t)d * OUT2 + j];
    const int pB = g_off[d], pE = g_off[d + 1];
    for (int p0 = pB; p0 < pE; p0 += 128) {
        int np = min(128, pE - p0);
        __syncthreads();
        if (j < np) {
            int s = g_csrc[p0 + j];
            ssrc[j] = s;
            sw[j] = lrelu_exp(g_as2[s] + add);
        }
        __syncthreads();
        #pragma unroll 4
        for (int e = 0; e < np; e++) {
            int s = ssrc[e];
            float wp = sw[e];
            den += wp;
            acc += wp * g_h2[(size_t)s * OUT2 + j];
        }
    }
    out[(size_t)d * OUT2 + j] = acc / den + b2[j];
}

extern "C" void kernel_launch(void* const* d_in, const int* in_sizes, int n_in,
                              void* d_out, int out_size) {
    const float* x    = (const float*)d_in[0];
    const void*  ei   = d_in[1];
    const float* W1   = (const float*)d_in[2];
    const float* as1  = (const float*)d_in[3];
    const float* ad1  = (const float*)d_in[4];
    const float* b1   = (const float*)d_in[5];
    const float* W2   = (const float*)d_in[6];
    const float* as2  = (const float*)d_in[7];
    const float* ad2  = (const float*)d_in[8];
    const float* b2   = (const float*)d_in[9];
    float* out = (float*)d_out;

    const int n_nodes = in_sizes[0] / NF;
    const int E  = in_sizes[1] / 2;

    const int eb = (E + 255) / 256;
    const int nb = (n_nodes + 1023) / 1024;

    static int smem_set = 0;
    if (!smem_set) {
        cudaFuncSetAttribute(k1_gemm1, cudaFuncAttributeMaxDynamicSharedMemorySize, K1_SMEM);
        smem_set = 1;
    }

    dim3 g1((n_nodes + 63) / 64, HH / 64);

    kz<<<nb + 1, 1024>>>((const int*)ei, E, n_nodes);          // 1
    kc2_count<<<eb, 256>>>(ei, E);                             // 2
    kv<<<6, 256>>>(W1, as1, ad1, W2, as2, ad2);                // 3
    k1_gemm1<<<g1, 256, K1_SMEM>>>(x, W1, n_nodes);            // 4  <- profiled slot
    ks_alpha1<<<(n_nodes + 31) / 32, 256>>>(x, n_nodes);       // 5
    s1_scan<<<nb, 1024>>>(n_nodes);                            // 6
    s2_scan<<<1, 32>>>(nb);                                    // 7
    s3_scan<<<nb, 1024>>>(n_nodes, E);                         // 8
    kc3w1<<<eb, 256>>>(ei, E);                                 // 9
    ka1<<<n_nodes, 256>>>(n_nodes);                            // 10
    k4_gemm2<<<(n_nodes + 31) / 32, 256>>>(W2, b1, n_nodes);   // 11
    ka2<<<n_nodes, 128>>>(n_nodes, b2, out);                   // 12
}